// round 5
// baseline (speedup 1.0000x reference)
#include <cuda_runtime.h>
#include <cuda_fp16.h>
#include <math.h>

#define NN 50000
#define EE 1600000
#define HIN 7
#define HH 128
#define FCC 256
#define CC 2
#define GG 512

// ---------------- scratch (device globals; no allocation in launch) ----------
__device__ float g_h [NN*HH];                    // node features (fp32)
__device__ __align__(16) __half g_xlh[NN*HH];    // source-transform, HALF (edge-gathered)
__device__ float g_xr[NN*HH];                    // target-transform (fp32)
__device__ int   g_off[NN+1];
__device__ int   g_cur[NN];
__device__ int   g_csrc[EE];
__device__ float g_pool[GG*HH];
__device__ int   g_cnt[GG];

__device__ __forceinline__ float lrelu02(float x){ return x > 0.f ? x : 0.2f*x; }
__device__ __forceinline__ float eluf(float x){ return x > 0.f ? x : (__expf(x) - 1.f); }

// unpack 4 halves (uint2) -> float4
__device__ __forceinline__ float4 h4_to_f4(uint2 u) {
    __half2 h0 = *reinterpret_cast<__half2*>(&u.x);
    __half2 h1 = *reinterpret_cast<__half2*>(&u.y);
    float2 f0 = __half22float2(h0);
    float2 f1 = __half22float2(h1);
    return make_float4(f0.x, f0.y, f1.x, f1.y);
}

// ---------------- CSR build --------------------------------------------------
__global__ void k_init() {
    int i = blockIdx.x*blockDim.x + threadIdx.x;
    if (i < NN)    g_cur[i]  = 0;
    if (i < GG*HH) g_pool[i] = 0.f;
    if (i < GG)    g_cnt[i]  = 0;
}

__global__ void k_hist(const int* __restrict__ ei) {
    int i = blockIdx.x*blockDim.x + threadIdx.x;
    if (i < EE/4) {
        int4 d = ((const int4*)(ei + EE))[i];
        atomicAdd(&g_cur[d.x], 1);
        atomicAdd(&g_cur[d.y], 1);
        atomicAdd(&g_cur[d.z], 1);
        atomicAdd(&g_cur[d.w], 1);
    }
}

__global__ void k_scan() {
    __shared__ int sums[1024];
    const int t = threadIdx.x;
    const int PER = (NN + 1023) / 1024;
    int base = t * PER;
    int local = 0;
    for (int k = 0; k < PER; k++) { int i = base + k; if (i < NN) local += g_cur[i]; }
    __syncthreads();
    sums[t] = local; __syncthreads();
    for (int d = 1; d < 1024; d <<= 1) {
        int v = (t >= d) ? sums[t - d] : 0;
        __syncthreads();
        sums[t] += v;
        __syncthreads();
    }
    int prefix = (t == 0) ? 0 : sums[t - 1];
    for (int k = 0; k < PER; k++) {
        int i = base + k;
        if (i < NN) {
            int d = g_cur[i];
            g_off[i] = prefix;
            g_cur[i] = prefix;
            prefix += d;
        }
    }
    if (t == 1023) g_off[NN] = prefix;
}

__global__ void k_scatter(const int* __restrict__ ei) {
    int i = blockIdx.x*blockDim.x + threadIdx.x;
    if (i >= EE) return;
    int s = ei[i];
    int d = ei[EE + i];
    int pos = atomicAdd(&g_cur[d], 1);
    g_csrc[pos] = s;
}

// ---------------- layer 0 linear (K=7) ---------------------------------------
__global__ __launch_bounds__(128) void k_lin0(const float* __restrict__ x,
                                              const float* __restrict__ Wl, const float* __restrict__ bl,
                                              const float* __restrict__ Wr, const float* __restrict__ br) {
    __shared__ float xs[32*HIN];
    const int t = threadIdx.x;
    const int n0 = blockIdx.x * 32;
    for (int i = t; i < 32*HIN; i += 128) {
        int n = n0 + i / HIN;
        xs[i] = (n < NN) ? x[n*HIN + (i % HIN)] : 0.f;
    }
    __syncthreads();
    float wl[HIN], wr[HIN];
#pragma unroll
    for (int k = 0; k < HIN; k++) { wl[k] = Wl[k*HH + t]; wr[k] = Wr[k*HH + t]; }
    float blv = bl[t], brv = br[t];
    for (int nn = 0; nn < 32; nn++) {
        int n = n0 + nn;
        if (n >= NN) break;
        float al = blv, ar = brv;
#pragma unroll
        for (int k = 0; k < HIN; k++) {
            float xv = xs[nn*HIN + k];
            al += xv * wl[k];
            ar += xv * wr[k];
        }
        g_xlh[n*HH + t] = __float2half_rn(al);
        g_xr [n*HH + t] = ar;
    }
}

// ---------------- linear (K=128), one of xl/xr per blockIdx.y ----------------
// 64 rows x 128 cols / block, 256 threads, 8x4 micro-tile.
__global__ __launch_bounds__(256) void k_lin(const float* __restrict__ Wl, const float* __restrict__ bl,
                                             const float* __restrict__ Wr, const float* __restrict__ br) {
    __shared__ float As[32][64];
    __shared__ float Ws[32*128];
    const int t    = threadIdx.x;
    const int row0 = blockIdx.x * 64;
    const bool left = (blockIdx.y == 0);
    const float* __restrict__ W = left ? Wl : Wr;
    const float* __restrict__ b = left ? bl : br;

    const int tc = t & 31;
    const int tr = t >> 5;
    float acc[8][4];
#pragma unroll
    for (int i = 0; i < 8; i++)
#pragma unroll
        for (int j = 0; j < 4; j++) acc[i][j] = 0.f;

    for (int kt = 0; kt < HH; kt += 32) {
#pragma unroll
        for (int task = t; task < 512; task += 256) {
            int kq = task >> 6;
            int r  = task & 63;
            int row = row0 + r;
            float4 v = make_float4(0.f, 0.f, 0.f, 0.f);
            if (row < NN) v = *(const float4*)(g_h + row*HH + kt + kq*4);
            As[kq*4+0][r] = v.x; As[kq*4+1][r] = v.y;
            As[kq*4+2][r] = v.z; As[kq*4+3][r] = v.w;
        }
#pragma unroll
        for (int q = 0; q < 4; q++) {
            int s  = t + 256*q;
            int k  = s >> 5;
            int c4 = (s & 31) * 4;
            *(float4*)(Ws + k*128 + c4) = *(const float4*)(W + (kt + k)*HH + c4);
        }
        __syncthreads();
#pragma unroll
        for (int k = 0; k < 32; k++) {
            float4 a0 = *(const float4*)&As[k][tr*8];
            float4 a1 = *(const float4*)&As[k][tr*8 + 4];
            float4 bv = *(const float4*)&Ws[k*128 + tc*4];
            float a[8] = {a0.x,a0.y,a0.z,a0.w,a1.x,a1.y,a1.z,a1.w};
#pragma unroll
            for (int i = 0; i < 8; i++) {
                acc[i][0] += a[i]*bv.x;
                acc[i][1] += a[i]*bv.y;
                acc[i][2] += a[i]*bv.z;
                acc[i][3] += a[i]*bv.w;
            }
        }
        __syncthreads();
    }

    float4 bv = *(const float4*)(b + tc*4);
    if (left) {
#pragma unroll
        for (int i = 0; i < 8; i++) {
            int row = row0 + tr*8 + i;
            if (row >= NN) continue;
            __half2 p0 = __floats2half2_rn(acc[i][0]+bv.x, acc[i][1]+bv.y);
            __half2 p1 = __floats2half2_rn(acc[i][2]+bv.z, acc[i][3]+bv.w);
            uint2 u;
            u.x = *reinterpret_cast<unsigned*>(&p0);
            u.y = *reinterpret_cast<unsigned*>(&p1);
            *((uint2*)(g_xlh + (size_t)row*HH) + tc) = u;
        }
    } else {
#pragma unroll
        for (int i = 0; i < 8; i++) {
            int row = row0 + tr*8 + i;
            if (row >= NN) continue;
            float4 o = make_float4(acc[i][0]+bv.x, acc[i][1]+bv.y, acc[i][2]+bv.z, acc[i][3]+bv.w);
            *(float4*)(g_xr + row*HH + tc*4) = o;
        }
    }
}

// ---------------- fused edge attention + ONLINE softmax + aggregate ----------
// one warp per destination node; fp16 source gathers (8B/lane), fp32 math.
__global__ __launch_bounds__(256) void k_edge(const float* __restrict__ att,
                                              const float* __restrict__ bo) {
    const int gw   = (blockIdx.x * 256 + threadIdx.x) >> 5;
    const int lane = threadIdx.x & 31;
    if (gw >= NN) return;
    const int dst = gw;

    const uint2* __restrict__ xlh = (const uint2*)g_xlh;   // 32 uint2 per row
    const float4* __restrict__ xrv = (const float4*)g_xr;

    float4 a4  = *(const float4*)(att + lane*4);
    float4 xr4 = xrv[dst*32 + lane];
    float4 xd4 = h4_to_f4(xlh[(size_t)dst*32 + lane]);     // xl[dst] (self-loop)

    float p = a4.x*lrelu02(xd4.x + xr4.x) + a4.y*lrelu02(xd4.y + xr4.y)
            + a4.z*lrelu02(xd4.z + xr4.z) + a4.w*lrelu02(xd4.w + xr4.w);
#pragma unroll
    for (int o = 16; o > 0; o >>= 1) p += __shfl_xor_sync(0xffffffffu, p, o);

    float m = p, s = 1.0f;
    float4 acc = xd4;

    const int beg = g_off[dst], end = g_off[dst + 1];
    int j = beg;

    for (; j + 2 <= end; j += 2) {
        int sn0 = g_csrc[j];
        int sn1 = g_csrc[j+1];
        float4 v0 = h4_to_f4(xlh[(size_t)sn0*32 + lane]);
        float4 v1 = h4_to_f4(xlh[(size_t)sn1*32 + lane]);

        float q0 = a4.x*lrelu02(v0.x + xr4.x) + a4.y*lrelu02(v0.y + xr4.y)
                 + a4.z*lrelu02(v0.z + xr4.z) + a4.w*lrelu02(v0.w + xr4.w);
        float q1 = a4.x*lrelu02(v1.x + xr4.x) + a4.y*lrelu02(v1.y + xr4.y)
                 + a4.z*lrelu02(v1.z + xr4.z) + a4.w*lrelu02(v1.w + xr4.w);
#pragma unroll
        for (int o = 16; o > 0; o >>= 1) {
            q0 += __shfl_xor_sync(0xffffffffu, q0, o);
            q1 += __shfl_xor_sync(0xffffffffu, q1, o);
        }

        if (q0 > m) {
            float r = __expf(m - q0);
            s = s*r + 1.0f;
            acc.x = acc.x*r + v0.x; acc.y = acc.y*r + v0.y;
            acc.z = acc.z*r + v0.z; acc.w = acc.w*r + v0.w;
            m = q0;
        } else {
            float w = __expf(q0 - m);
            s += w;
            acc.x += w*v0.x; acc.y += w*v0.y;
            acc.z += w*v0.z; acc.w += w*v0.w;
        }
        if (q1 > m) {
            float r = __expf(m - q1);
            s = s*r + 1.0f;
            acc.x = acc.x*r + v1.x; acc.y = acc.y*r + v1.y;
            acc.z = acc.z*r + v1.z; acc.w = acc.w*r + v1.w;
            m = q1;
        } else {
            float w = __expf(q1 - m);
            s += w;
            acc.x += w*v1.x; acc.y += w*v1.y;
            acc.z += w*v1.z; acc.w += w*v1.w;
        }
    }

    if (j < end) {
        int sn = g_csrc[j];
        float4 v = h4_to_f4(xlh[(size_t)sn*32 + lane]);
        float q = a4.x*lrelu02(v.x + xr4.x) + a4.y*lrelu02(v.y + xr4.y)
                + a4.z*lrelu02(v.z + xr4.z) + a4.w*lrelu02(v.w + xr4.w);
#pragma unroll
        for (int o = 16; o > 0; o >>= 1) q += __shfl_xor_sync(0xffffffffu, q, o);
        if (q > m) {
            float r = __expf(m - q);
            s = s*r + 1.0f;
            acc.x = acc.x*r + v.x; acc.y = acc.y*r + v.y;
            acc.z = acc.z*r + v.z; acc.w = acc.w*r + v.w;
            m = q;
        } else {
            float w = __expf(q - m);
            s += w;
            acc.x += w*v.x; acc.y += w*v.y;
            acc.z += w*v.z; acc.w += w*v.w;
        }
    }

    const float inv = 1.0f / s;
    float4 b4 = *(const float4*)(bo + lane*4);
    float4 o;
    o.x = eluf(acc.x*inv + b4.x); o.y = eluf(acc.y*inv + b4.y);
    o.z = eluf(acc.z*inv + b4.z); o.w = eluf(acc.w*inv + b4.w);
    ((float4*)g_h)[dst*32 + lane] = o;
}

// ---------------- global mean pool (run-length compressed atomics) -----------
__global__ __launch_bounds__(256) void k_pool(const int* __restrict__ batch) {
    const int warp = (blockIdx.x * 256 + threadIdx.x) >> 5;
    const int lane = threadIdx.x & 31;
    const int n0 = warp * 32;
    if (n0 >= NN) return;
    const int n1 = min(n0 + 32, NN);

    const float4* __restrict__ hv = (const float4*)g_h;

    int curg = -1, run = 0;
    float4 acc = make_float4(0.f,0.f,0.f,0.f);

    for (int node = n0; node < n1; node++) {
        int g = batch[node];
        if (g != curg) {
            if (run > 0) {
                atomicAdd(&g_pool[curg*HH + lane*4 + 0], acc.x);
                atomicAdd(&g_pool[curg*HH + lane*4 + 1], acc.y);
                atomicAdd(&g_pool[curg*HH + lane*4 + 2], acc.z);
                atomicAdd(&g_pool[curg*HH + lane*4 + 3], acc.w);
                if (lane == 0) atomicAdd(&g_cnt[curg], run);
            }
            curg = g; run = 0;
            acc = make_float4(0.f,0.f,0.f,0.f);
        }
        float4 v = hv[node*32 + lane];
        acc.x += v.x; acc.y += v.y; acc.z += v.z; acc.w += v.w;
        run++;
    }
    if (run > 0) {
        atomicAdd(&g_pool[curg*HH + lane*4 + 0], acc.x);
        atomicAdd(&g_pool[curg*HH + lane*4 + 1], acc.y);
        atomicAdd(&g_pool[curg*HH + lane*4 + 2], acc.z);
        atomicAdd(&g_pool[curg*HH + lane*4 + 3], acc.w);
        if (lane == 0) atomicAdd(&g_cnt[curg], run);
    }
}

// ---------------- MLP head + log_softmax -------------------------------------
__global__ __launch_bounds__(128) void k_head(const float* __restrict__ fc1W, const float* __restrict__ fc1b,
                                              const float* __restrict__ fc2W, const float* __restrict__ fc2b,
                                              float* __restrict__ out) {
    __shared__ float gs[HH];
    __shared__ float red0[128], red1[128];
    const int gid = blockIdx.x;
    const int t = threadIdx.x;
    float c = (float)g_cnt[gid];
    if (c < 1.f) c = 1.f;
    gs[t] = g_pool[gid*HH + t] / c;
    __syncthreads();
    float p0 = 0.f, p1 = 0.f;
    for (int cc = t; cc < FCC; cc += 128) {
        float z = fc1b[cc];
        for (int k = 0; k < HH; k++) z += gs[k] * fc1W[k*FCC + cc];
        z = fmaxf(z, 0.f);
        p0 += z * fc2W[cc*CC + 0];
        p1 += z * fc2W[cc*CC + 1];
    }
    red0[t] = p0; red1[t] = p1;
    __syncthreads();
    for (int st = 64; st > 0; st >>= 1) {
        if (t < st) { red0[t] += red0[t + st]; red1[t] += red1[t + st]; }
        __syncthreads();
    }
    if (t == 0) {
        float l0 = red0[0] + fc2b[0];
        float l1 = red1[0] + fc2b[1];
        float mm  = fmaxf(l0, l1);
        float lse = mm + logf(__expf(l0 - mm) + __expf(l1 - mm));
        out[gid*CC + 0] = l0 - lse;
        out[gid*CC + 1] = l1 - lse;
    }
}

// ---------------- launch ------------------------------------------------------
extern "C" void kernel_launch(void* const* d_in, const int* in_sizes, int n_in,
                              void* d_out, int out_size) {
    const float* x     = (const float*)d_in[0];
    const int*   ei    = (const int*)  d_in[1];
    const int*   batch = (const int*)  d_in[2];
    const float* Wl0 = (const float*)d_in[3];  const float* bl0 = (const float*)d_in[4];
    const float* Wr0 = (const float*)d_in[5];  const float* br0 = (const float*)d_in[6];
    const float* at0 = (const float*)d_in[7];  const float* bo0 = (const float*)d_in[8];
    const float* Wl1 = (const float*)d_in[9];  const float* bl1 = (const float*)d_in[10];
    const float* Wr1 = (const float*)d_in[11]; const float* br1 = (const float*)d_in[12];
    const float* at1 = (const float*)d_in[13]; const float* bo1 = (const float*)d_in[14];
    const float* Wl2 = (const float*)d_in[15]; const float* bl2 = (const float*)d_in[16];
    const float* Wr2 = (const float*)d_in[17]; const float* br2 = (const float*)d_in[18];
    const float* at2 = (const float*)d_in[19]; const float* bo2 = (const float*)d_in[20];
    const float* fc1W = (const float*)d_in[21]; const float* fc1b = (const float*)d_in[22];
    const float* fc2W = (const float*)d_in[23]; const float* fc2b = (const float*)d_in[24];
    float* out = (float*)d_out;

    dim3 ling((NN + 63)/64, 2);

    k_init   <<<(GG*HH + 255)/256, 256>>>();
    k_hist   <<<(EE/4 + 255)/256, 256>>>(ei);
    k_scan   <<<1, 1024>>>();
    k_scatter<<<(EE + 255)/256, 256>>>(ei);

    k_lin0<<<(NN + 31)/32, 128>>>(x, Wl0, bl0, Wr0, br0);
    k_edge<<<(NN + 7)/8, 256>>>(at0, bo0);

    k_lin <<<ling, 256>>>(Wl1, bl1, Wr1, br1);
    k_edge<<<(NN + 7)/8, 256>>>(at1, bo1);

    k_lin <<<ling, 256>>>(Wl2, bl2, Wr2, br2);
    k_edge<<<(NN + 7)/8, 256>>>(at2, bo2);

    k_pool<<<(NN + 7)/8, 256>>>(batch);
    k_head<<<GG, 128>>>(fc1W, fc1b, fc2W, fc2b, out);
}

// round 6
// speedup vs baseline: 1.1743x; 1.1743x over previous
#include <cuda_runtime.h>
#include <cuda_fp16.h>
#include <math.h>

#define NN 50000
#define EE 1600000
#define HIN 7
#define HH 128
#define FCC 256
#define CC 2
#define GG 512

// ---------------- scratch (device globals; no allocation in launch) ----------
__device__ float g_h [NN*HH];                    // node features (fp32)
__device__ __align__(16) __half g_xlh[NN*HH];    // source-transform (half)
__device__ __align__(16) __half g_xrh[NN*HH];    // target-transform (half)
__device__ int   g_off[NN+1];
__device__ int   g_cur[NN];
__device__ int   g_csrc[EE];
__device__ float g_pool[GG*HH];
__device__ int   g_cnt[GG];

__device__ __forceinline__ float eluf(float x){ return x > 0.f ? x : (__expf(x) - 1.f); }

// ---------------- CSR init ----------------------------------------------------
__global__ void k_init() {
    int i = blockIdx.x*blockDim.x + threadIdx.x;
    if (i < NN)    g_cur[i]  = 0;
    if (i < GG*HH) g_pool[i] = 0.f;
    if (i < GG)    g_cnt[i]  = 0;
}

// ---------------- fused: edge histogram (blocks [0,HB)) + layer0 linear ------
#define HB ((EE/4 + 255)/256)    // 1563 histogram blocks
__global__ __launch_bounds__(256) void k_hist_lin0(const int* __restrict__ ei,
                                                   const float* __restrict__ x,
                                                   const float* __restrict__ Wl, const float* __restrict__ bl,
                                                   const float* __restrict__ Wr, const float* __restrict__ br) {
    if (blockIdx.x < HB) {
        int i = blockIdx.x*256 + threadIdx.x;
        if (i < EE/4) {
            int4 d = ((const int4*)(ei + EE))[i];
            atomicAdd(&g_cur[d.x], 1);
            atomicAdd(&g_cur[d.y], 1);
            atomicAdd(&g_cur[d.z], 1);
            atomicAdd(&g_cur[d.w], 1);
        }
        return;
    }
    // layer-0 linear: 64 nodes per block, 256 threads (2 groups x 128 cols)
    __shared__ float xs[64*HIN];
    const int bb = blockIdx.x - HB;
    const int n0 = bb * 64;
    const int t  = threadIdx.x;
    for (int i = t; i < 64*HIN; i += 256) {
        int n = n0 + i / HIN;
        xs[i] = (n < NN) ? x[n*HIN + (i % HIN)] : 0.f;
    }
    __syncthreads();
    const int col = t & 127;
    const int grp = t >> 7;         // 0/1 -> nodes [n0+grp*32, +32)
    float wl[HIN], wr[HIN];
#pragma unroll
    for (int k = 0; k < HIN; k++) { wl[k] = Wl[k*HH + col]; wr[k] = Wr[k*HH + col]; }
    float blv = bl[col], brv = br[col];
    for (int nn = 0; nn < 32; nn++) {
        int n = n0 + grp*32 + nn;
        if (n >= NN) break;
        float al = blv, ar = brv;
#pragma unroll
        for (int k = 0; k < HIN; k++) {
            float xv = xs[(grp*32 + nn)*HIN + k];
            al += xv * wl[k];
            ar += xv * wr[k];
        }
        g_xlh[(size_t)n*HH + col] = __float2half_rn(al);
        g_xrh[(size_t)n*HH + col] = __float2half_rn(ar);
    }
}

// ---------------- scan (also seeds scatter cursors) ---------------------------
__global__ void k_scan() {
    __shared__ int sums[1024];
    const int t = threadIdx.x;
    const int PER = (NN + 1023) / 1024;
    int base = t * PER;
    int local = 0;
    for (int k = 0; k < PER; k++) { int i = base + k; if (i < NN) local += g_cur[i]; }
    __syncthreads();
    sums[t] = local; __syncthreads();
    for (int d = 1; d < 1024; d <<= 1) {
        int v = (t >= d) ? sums[t - d] : 0;
        __syncthreads();
        sums[t] += v;
        __syncthreads();
    }
    int prefix = (t == 0) ? 0 : sums[t - 1];
    for (int k = 0; k < PER; k++) {
        int i = base + k;
        if (i < NN) {
            int d = g_cur[i];
            g_off[i] = prefix;
            g_cur[i] = prefix;
            prefix += d;
        }
    }
    if (t == 1023) g_off[NN] = prefix;
}

__global__ void k_scatter(const int* __restrict__ ei) {
    int i = blockIdx.x*blockDim.x + threadIdx.x;
    if (i >= EE) return;
    int s = ei[i];
    int d = ei[EE + i];
    int pos = atomicAdd(&g_cur[d], 1);
    g_csrc[pos] = s;
}

// ---------------- linear (K=128): h@W+b -> half output -----------------------
// 64 rows x 128 cols / block, 256 threads, 8x4 micro-tile; blockIdx.y: 0=xl,1=xr
__global__ __launch_bounds__(256) void k_lin(const float* __restrict__ Wl, const float* __restrict__ bl,
                                             const float* __restrict__ Wr, const float* __restrict__ br) {
    __shared__ float As[32][64];
    __shared__ float Ws[32*128];
    const int t    = threadIdx.x;
    const int row0 = blockIdx.x * 64;
    const bool left = (blockIdx.y == 0);
    const float* __restrict__ W = left ? Wl : Wr;
    const float* __restrict__ b = left ? bl : br;
    __half* __restrict__ outh   = left ? g_xlh : g_xrh;

    const int tc = t & 31;
    const int tr = t >> 5;
    float acc[8][4];
#pragma unroll
    for (int i = 0; i < 8; i++)
#pragma unroll
        for (int j = 0; j < 4; j++) acc[i][j] = 0.f;

    for (int kt = 0; kt < HH; kt += 32) {
#pragma unroll
        for (int task = t; task < 512; task += 256) {
            int kq = task >> 6;
            int r  = task & 63;
            int row = row0 + r;
            float4 v = make_float4(0.f, 0.f, 0.f, 0.f);
            if (row < NN) v = *(const float4*)(g_h + (size_t)row*HH + kt + kq*4);
            As[kq*4+0][r] = v.x; As[kq*4+1][r] = v.y;
            As[kq*4+2][r] = v.z; As[kq*4+3][r] = v.w;
        }
#pragma unroll
        for (int q = 0; q < 4; q++) {
            int s  = t + 256*q;
            int k  = s >> 5;
            int c4 = (s & 31) * 4;
            *(float4*)(Ws + k*128 + c4) = *(const float4*)(W + (kt + k)*HH + c4);
        }
        __syncthreads();
#pragma unroll
        for (int k = 0; k < 32; k++) {
            float4 a0 = *(const float4*)&As[k][tr*8];
            float4 a1 = *(const float4*)&As[k][tr*8 + 4];
            float4 bv = *(const float4*)&Ws[k*128 + tc*4];
            float a[8] = {a0.x,a0.y,a0.z,a0.w,a1.x,a1.y,a1.z,a1.w};
#pragma unroll
            for (int i = 0; i < 8; i++) {
                acc[i][0] += a[i]*bv.x;
                acc[i][1] += a[i]*bv.y;
                acc[i][2] += a[i]*bv.z;
                acc[i][3] += a[i]*bv.w;
            }
        }
        __syncthreads();
    }

    float4 bv = *(const float4*)(b + tc*4);
#pragma unroll
    for (int i = 0; i < 8; i++) {
        int row = row0 + tr*8 + i;
        if (row >= NN) continue;
        __half2 p0 = __floats2half2_rn(acc[i][0]+bv.x, acc[i][1]+bv.y);
        __half2 p1 = __floats2half2_rn(acc[i][2]+bv.z, acc[i][3]+bv.w);
        uint2 u;
        u.x = *reinterpret_cast<unsigned*>(&p0);
        u.y = *reinterpret_cast<unsigned*>(&p1);
        *((uint2*)(outh + (size_t)row*HH) + tc) = u;
    }
}

// ---------------- fused edge attention: half2 SIMD, online softmax -----------
// one warp per dst; 2 edges per iteration; both edges' logits reduced in ONE
// packed half2 butterfly (2.5 shuffles/edge).
__global__ __launch_bounds__(256) void k_edge(const float* __restrict__ att,
                                              const float* __restrict__ bo) {
    const int gw   = (blockIdx.x * 256 + threadIdx.x) >> 5;
    const int lane = threadIdx.x & 31;
    if (gw >= NN) return;
    const int dst = gw;

    const uint2* __restrict__ xl2 = (const uint2*)g_xlh;
    const uint2* __restrict__ xr2 = (const uint2*)g_xrh;

    float4 a4 = *(const float4*)(att + lane*4);
    const __half2 at0 = __floats2half2_rn(a4.x, a4.y);
    const __half2 at1 = __floats2half2_rn(a4.z, a4.w);
    const __half2 c02 = __float2half2_rn(0.2f);

    uint2 xru = xr2[(size_t)dst*32 + lane];
    const __half2 xr0 = *reinterpret_cast<__half2*>(&xru.x);
    const __half2 xr1 = *reinterpret_cast<__half2*>(&xru.y);

    uint2 xdu = xl2[(size_t)dst*32 + lane];
    const __half2 xd0 = *reinterpret_cast<__half2*>(&xdu.x);
    const __half2 xd1 = *reinterpret_cast<__half2*>(&xdu.y);

    // self-loop logit
    {
    }
    __half2 u0 = __hadd2(xd0, xr0), u1 = __hadd2(xd1, xr1);
    u0 = __hmax2(u0, __hmul2(u0, c02));
    u1 = __hmax2(u1, __hmul2(u1, c02));
    __half2 pp = __hmul2(at0, u0); pp = __hfma2(at1, u1, pp);
    float pf = __low2float(pp) + __high2float(pp);
#pragma unroll
    for (int o = 16; o > 0; o >>= 1) pf += __shfl_xor_sync(0xffffffffu, pf, o);

    float m = pf, s = 1.0f;
    __half2 acc0 = xd0, acc1 = xd1;   // self-loop contribution (weight 1)

    const int beg = g_off[dst], end = g_off[dst + 1];
    int j = beg;

    for (; j + 2 <= end; j += 2) {
        int snA = g_csrc[j];
        int snB = g_csrc[j+1];
        uint2 uA = xl2[(size_t)snA*32 + lane];
        uint2 uB = xl2[(size_t)snB*32 + lane];
        __half2 vA0 = *reinterpret_cast<__half2*>(&uA.x);
        __half2 vA1 = *reinterpret_cast<__half2*>(&uA.y);
        __half2 vB0 = *reinterpret_cast<__half2*>(&uB.x);
        __half2 vB1 = *reinterpret_cast<__half2*>(&uB.y);

        __half2 tA0 = __hadd2(vA0, xr0), tA1 = __hadd2(vA1, xr1);
        __half2 tB0 = __hadd2(vB0, xr0), tB1 = __hadd2(vB1, xr1);
        tA0 = __hmax2(tA0, __hmul2(tA0, c02));
        tA1 = __hmax2(tA1, __hmul2(tA1, c02));
        tB0 = __hmax2(tB0, __hmul2(tB0, c02));
        tB1 = __hmax2(tB1, __hmul2(tB1, c02));
        __half2 pA = __hmul2(at0, tA0); pA = __hfma2(at1, tA1, pA);
        __half2 pB = __hmul2(at0, tB0); pB = __hfma2(at1, tB1, pB);

        // pack both edges' partials: qp = (pA.x+pA.y, pB.x+pB.y)
        __half2 qlo = __halves2half2(__low2half(pA),  __low2half(pB));
        __half2 qhi = __halves2half2(__high2half(pA), __high2half(pB));
        __half2 qp  = __hadd2(qlo, qhi);
#pragma unroll
        for (int o = 16; o > 0; o >>= 1) {
            unsigned xv = __shfl_xor_sync(0xffffffffu, *reinterpret_cast<unsigned*>(&qp), o);
            qp = __hadd2(qp, *reinterpret_cast<__half2*>(&xv));
        }
        float2 qf = __half22float2(qp);

        // edge A update (warp-uniform branches)
        if (qf.x > m) {
            float r = __expf(m - qf.x); m = qf.x;
            s = s*r + 1.0f;
            __half2 r2 = __float2half2_rn(r);
            acc0 = __hfma2(acc0, r2, vA0);
            acc1 = __hfma2(acc1, r2, vA1);
        } else {
            float w = __expf(qf.x - m); s += w;
            __half2 w2 = __float2half2_rn(w);
            acc0 = __hfma2(w2, vA0, acc0);
            acc1 = __hfma2(w2, vA1, acc1);
        }
        // edge B update
        if (qf.y > m) {
            float r = __expf(m - qf.y); m = qf.y;
            s = s*r + 1.0f;
            __half2 r2 = __float2half2_rn(r);
            acc0 = __hfma2(acc0, r2, vB0);
            acc1 = __hfma2(acc1, r2, vB1);
        } else {
            float w = __expf(qf.y - m); s += w;
            __half2 w2 = __float2half2_rn(w);
            acc0 = __hfma2(w2, vB0, acc0);
            acc1 = __hfma2(w2, vB1, acc1);
        }
    }

    if (j < end) {   // tail edge
        int sn = g_csrc[j];
        uint2 uu = xl2[(size_t)sn*32 + lane];
        __half2 v0 = *reinterpret_cast<__half2*>(&uu.x);
        __half2 v1 = *reinterpret_cast<__half2*>(&uu.y);
        __half2 t0 = __hadd2(v0, xr0), t1 = __hadd2(v1, xr1);
        t0 = __hmax2(t0, __hmul2(t0, c02));
        t1 = __hmax2(t1, __hmul2(t1, c02));
        __half2 pq = __hmul2(at0, t0); pq = __hfma2(at1, t1, pq);
        float q = __low2float(pq) + __high2float(pq);
#pragma unroll
        for (int o = 16; o > 0; o >>= 1) q += __shfl_xor_sync(0xffffffffu, q, o);
        if (q > m) {
            float r = __expf(m - q); m = q;
            s = s*r + 1.0f;
            __half2 r2 = __float2half2_rn(r);
            acc0 = __hfma2(acc0, r2, v0);
            acc1 = __hfma2(acc1, r2, v1);
        } else {
            float w = __expf(q - m); s += w;
            __half2 w2 = __float2half2_rn(w);
            acc0 = __hfma2(w2, v0, acc0);
            acc1 = __hfma2(w2, v1, acc1);
        }
    }

    const float inv = 1.0f / s;
    float4 b4 = *(const float4*)(bo + lane*4);
    float2 f0 = __half22float2(acc0);
    float2 f1 = __half22float2(acc1);
    float4 o;
    o.x = eluf(f0.x*inv + b4.x); o.y = eluf(f0.y*inv + b4.y);
    o.z = eluf(f1.x*inv + b4.z); o.w = eluf(f1.y*inv + b4.w);
    ((float4*)g_h)[(size_t)dst*32 + lane] = o;
}

// ---------------- global mean pool (run-length compressed atomics) -----------
__global__ __launch_bounds__(256) void k_pool(const int* __restrict__ batch) {
    const int warp = (blockIdx.x * 256 + threadIdx.x) >> 5;
    const int lane = threadIdx.x & 31;
    const int n0 = warp * 32;
    if (n0 >= NN) return;
    const int n1 = min(n0 + 32, NN);

    const float4* __restrict__ hv = (const float4*)g_h;

    int curg = -1, run = 0;
    float4 acc = make_float4(0.f,0.f,0.f,0.f);

    for (int node = n0; node < n1; node++) {
        int g = batch[node];
        if (g != curg) {
            if (run > 0) {
                atomicAdd(&g_pool[curg*HH + lane*4 + 0], acc.x);
                atomicAdd(&g_pool[curg*HH + lane*4 + 1], acc.y);
                atomicAdd(&g_pool[curg*HH + lane*4 + 2], acc.z);
                atomicAdd(&g_pool[curg*HH + lane*4 + 3], acc.w);
                if (lane == 0) atomicAdd(&g_cnt[curg], run);
            }
            curg = g; run = 0;
            acc = make_float4(0.f,0.f,0.f,0.f);
        }
        float4 v = hv[(size_t)node*32 + lane];
        acc.x += v.x; acc.y += v.y; acc.z += v.z; acc.w += v.w;
        run++;
    }
    if (run > 0) {
        atomicAdd(&g_pool[curg*HH + lane*4 + 0], acc.x);
        atomicAdd(&g_pool[curg*HH + lane*4 + 1], acc.y);
        atomicAdd(&g_pool[curg*HH + lane*4 + 2], acc.z);
        atomicAdd(&g_pool[curg*HH + lane*4 + 3], acc.w);
        if (lane == 0) atomicAdd(&g_cnt[curg], run);
    }
}

// ---------------- MLP head + log_softmax -------------------------------------
__global__ __launch_bounds__(128) void k_head(const float* __restrict__ fc1W, const float* __restrict__ fc1b,
                                              const float* __restrict__ fc2W, const float* __restrict__ fc2b,
                                              float* __restrict__ out) {
    __shared__ float gs[HH];
    __shared__ float red0[128], red1[128];
    const int gid = blockIdx.x;
    const int t = threadIdx.x;
    float c = (float)g_cnt[gid];
    if (c < 1.f) c = 1.f;
    gs[t] = g_pool[gid*HH + t] / c;
    __syncthreads();
    float p0 = 0.f, p1 = 0.f;
    for (int cc = t; cc < FCC; cc += 128) {
        float z = fc1b[cc];
        for (int k = 0; k < HH; k++) z += gs[k] * fc1W[k*FCC + cc];
        z = fmaxf(z, 0.f);
        p0 += z * fc2W[cc*CC + 0];
        p1 += z * fc2W[cc*CC + 1];
    }
    red0[t] = p0; red1[t] = p1;
    __syncthreads();
    for (int st = 64; st > 0; st >>= 1) {
        if (t < st) { red0[t] += red0[t + st]; red1[t] += red1[t + st]; }
        __syncthreads();
    }
    if (t == 0) {
        float l0 = red0[0] + fc2b[0];
        float l1 = red1[0] + fc2b[1];
        float mm  = fmaxf(l0, l1);
        float lse = mm + logf(__expf(l0 - mm) + __expf(l1 - mm));
        out[gid*CC + 0] = l0 - lse;
        out[gid*CC + 1] = l1 - lse;
    }
}

// ---------------- launch ------------------------------------------------------
extern "C" void kernel_launch(void* const* d_in, const int* in_sizes, int n_in,
                              void* d_out, int out_size) {
    const float* x     = (const float*)d_in[0];
    const int*   ei    = (const int*)  d_in[1];
    const int*   batch = (const int*)  d_in[2];
    const float* Wl0 = (const float*)d_in[3];  const float* bl0 = (const float*)d_in[4];
    const float* Wr0 = (const float*)d_in[5];  const float* br0 = (const float*)d_in[6];
    const float* at0 = (const float*)d_in[7];  const float* bo0 = (const float*)d_in[8];
    const float* Wl1 = (const float*)d_in[9];  const float* bl1 = (const float*)d_in[10];
    const float* Wr1 = (const float*)d_in[11]; const float* br1 = (const float*)d_in[12];
    const float* at1 = (const float*)d_in[13]; const float* bo1 = (const float*)d_in[14];
    const float* Wl2 = (const float*)d_in[15]; const float* bl2 = (const float*)d_in[16];
    const float* Wr2 = (const float*)d_in[17]; const float* br2 = (const float*)d_in[18];
    const float* at2 = (const float*)d_in[19]; const float* bo2 = (const float*)d_in[20];
    const float* fc1W = (const float*)d_in[21]; const float* fc1b = (const float*)d_in[22];
    const float* fc2W = (const float*)d_in[23]; const float* fc2b = (const float*)d_in[24];
    float* out = (float*)d_out;

    dim3 ling((NN + 63)/64, 2);
    const int L0B = (NN + 63)/64;          // 782 lin0 blocks

    k_init     <<<(GG*HH + 255)/256, 256>>>();
    k_hist_lin0<<<HB + L0B, 256>>>(ei, x, Wl0, bl0, Wr0, br0);
    k_scan     <<<1, 1024>>>();
    k_scatter  <<<(EE + 255)/256, 256>>>(ei);

    k_edge<<<(NN + 7)/8, 256>>>(at0, bo0);

    k_lin <<<ling, 256>>>(Wl1, bl1, Wr1, br1);
    k_edge<<<(NN + 7)/8, 256>>>(at1, bo1);

    k_lin <<<ling, 256>>>(Wl2, bl2, Wr2, br2);
    k_edge<<<(NN + 7)/8, 256>>>(at2, bo2);

    k_pool<<<(NN + 7)/8, 256>>>(batch);
    k_head<<<GG, 128>>>(fc1W, fc1b, fc2W, fc2b, out);
}